// round 13
// baseline (speedup 1.0000x reference)
#include <cuda_runtime.h>
#include <cstdint>

#define BB 2
#define HH 48
#define WW 48
#define CC 96
#define LL (HH*WW)        // 2304
#define DI 192
#define NS 32
#define RR 6
#define KK 4
#define NCH 6
#define CHL (LL/NCH)      // 384
#define L3 64             // k3 l-tile

// ---- scratch (device globals; no allocations allowed) ----
__device__ float  g_xraw  [BB*DI*LL];
__device__ float  g_xconv [BB*DI*LL];          // conv+silu, hw-order (b,d,l)
__device__ float  g_xconvT[BB*DI*LL];          // conv+silu, wh-order (b,d,j)
__device__ float  g_z     [BB*LL*DI];          // silu(z), (b,l,d)
__device__ float  g_dts   [BB*KK*RR*LL];       // (b,k,r,l)
__device__ float4 g_BC4   [BB*KK*(LL/2)*NS];   // (b,k,l/2,n) -> (B0,C0,B1,C1)
__device__ float2 g_Bn2   [BB*KK*(LL/2)*NS];   // (b,k,l/2,n) -> (B0,B1)
__device__ float2 g_du    [BB*KK*DI*LL];       // (delta,u) per (b,k,d,l)
__device__ float  g_y     [(size_t)BB*KK*LL*DI];
__device__ float  g_hfin  [BB*KK*DI*NCH*NS];
__device__ float  g_P     [BB*KK*DI*NCH*NS];
__device__ float  g_hin   [BB*KK*DI*NCH*NS];
__device__ float  g_opwT  [DI*CC];             // transposed out_proj [d][c]

// ===== K0: transpose out_proj weight (tiny, once per launch) =====
__global__ void __launch_bounds__(256) k0_transpose(const float* __restrict__ opw) {
    int idx = blockIdx.x * 256 + threadIdx.x;
    if (idx >= DI*CC) return;
    int d = idx / CC, c = idx % CC;
    g_opwT[idx] = opw[(size_t)c*DI + d];
}

// ================= K1: in_proj + split + silu(z) =================
__global__ void __launch_bounds__(256, 4) k1_inproj(const float* __restrict__ x,
                                                    const float* __restrict__ ipw) {
    __shared__ float sm[32][97];
    int bl = blockIdx.x;
    int lt = bl % (LL/32), b = bl / (LL/32);
    int l0 = lt * 32;
    int tid = threadIdx.x, lane = tid & 31, wid = tid >> 5;
    for (int i = tid; i < 32*96; i += 256) {
        int j = i / 96, c = i % 96;
        sm[j][c] = x[((size_t)b*LL + l0 + j)*CC + c];
    }
    __syncthreads();
    int e0 = (blockIdx.y * 8 + wid) * 6;
    float acc[6] = {0.f,0.f,0.f,0.f,0.f,0.f};
    #pragma unroll 4
    for (int c4 = 0; c4 < 24; c4++) {
        float s0 = sm[lane][c4*4+0], s1 = sm[lane][c4*4+1];
        float s2 = sm[lane][c4*4+2], s3 = sm[lane][c4*4+3];
        #pragma unroll
        for (int i = 0; i < 6; i++) {
            const float4 wv = *(const float4*)(ipw + (size_t)(e0+i)*CC + c4*4);
            acc[i] = fmaf(wv.x, s0, acc[i]);
            acc[i] = fmaf(wv.y, s1, acc[i]);
            acc[i] = fmaf(wv.z, s2, acc[i]);
            acc[i] = fmaf(wv.w, s3, acc[i]);
        }
    }
    int l = l0 + lane;
    #pragma unroll
    for (int i = 0; i < 6; i++) {
        int e = e0 + i;
        if (e < DI) {
            g_xraw[((size_t)b*DI + e)*LL + l] = acc[i];
        } else {
            float v = acc[i];
            g_z[((size_t)b*LL + l)*DI + (e - DI)] = v / (1.f + __expf(-v));
        }
    }
}

// ===== K2: depthwise conv 3x3 + bias + silu; writes hw AND wh layouts =====
__global__ void __launch_bounds__(256) k2_conv(const float* __restrict__ cw,
                                               const float* __restrict__ cb) {
    __shared__ float si[LL];
    __shared__ float so[HH*49];
    int bd = blockIdx.x;                 // = b*DI + d
    int d = bd % DI;
    int tid = threadIdx.x;
    const float* src = g_xraw + (size_t)bd * LL;
    for (int i = tid; i < LL; i += 256) si[i] = src[i];
    float wts[9];
    #pragma unroll
    for (int j = 0; j < 9; j++) wts[j] = cw[d*9 + j];
    float bias = cb[d];
    __syncthreads();
    for (int l = tid; l < LL; l += 256) {
        int h = l / WW, w = l % WW;
        float acc = bias;
        #pragma unroll
        for (int dh = -1; dh <= 1; dh++) {
            #pragma unroll
            for (int dw = -1; dw <= 1; dw++) {
                int hh = h + dh, ww2 = w + dw;
                if (hh >= 0 && hh < HH && ww2 >= 0 && ww2 < WW)
                    acc = fmaf(si[hh*WW + ww2], wts[(dh+1)*3 + (dw+1)], acc);
            }
        }
        float v = acc / (1.f + __expf(-acc));
        g_xconv[(size_t)bd*LL + l] = v;
        so[h*49 + w] = v;
    }
    __syncthreads();
    for (int j = tid; j < LL; j += 256) {     // j = w*HH + h
        int w = j / HH, h = j % HH;
        g_xconvT[(size_t)bd*LL + j] = so[h*49 + w];
    }
}

// ================= K3: x_proj, 64-l tiles, l-major smem (float4 LDS) ========
// grid (36, 8) = 288 CTAs ~ 2/SM. Per dd4: 9 weight LDG.128 + 2 LDS.128 + 72 FMA.
__global__ void __launch_bounds__(256) k3_xproj(const float* __restrict__ xpw) {
    __shared__ float sxl[L3][100];       // stride 100: 16B-aligned rows, cf reads
    int lt = blockIdx.x;                 // 0..35
    int bk = blockIdx.y;                 // 0..7
    int k = bk & 3, b = bk >> 2;
    int l0 = lt * L3;
    int tid = threadIdx.x, lane = tid & 31, wid = tid >> 5;
    const float* xbase = (k & 1) ? g_xconvT : g_xconv;

    float acc[9][2];
    #pragma unroll
    for (int i = 0; i < 9; i++) { acc[i][0] = 0.f; acc[i][1] = 0.f; }
    int cbase = wid;                     // c = wid + 8*i

    for (int p = 0; p < 2; p++) {        // d-chunks of 96
        __syncthreads();
        for (int i = tid; i < 96*L3; i += 256) {
            int dd = i >> 6, j = i & 63;
            int l = l0 + j;
            int idx = (k < 2) ? l : (LL - 1 - l);
            sxl[j][dd] = xbase[((size_t)b*DI + p*96 + dd)*LL + idx];
        }
        __syncthreads();
        #pragma unroll 2
        for (int dp = 0; dp < 24; dp++) {
            float4 xv0 = *(const float4*)&sxl[lane     ][dp*4];
            float4 xv1 = *(const float4*)&sxl[lane + 32][dp*4];
            #pragma unroll
            for (int i = 0; i < 9; i++) {
                int c = cbase + 8*i;
                if (c < 70) {
                    const float4 wv = *(const float4*)(xpw + ((size_t)(k*70 + c))*DI + p*96 + dp*4);
                    acc[i][0] = fmaf(wv.x, xv0.x, acc[i][0]);
                    acc[i][0] = fmaf(wv.y, xv0.y, acc[i][0]);
                    acc[i][0] = fmaf(wv.z, xv0.z, acc[i][0]);
                    acc[i][0] = fmaf(wv.w, xv0.w, acc[i][0]);
                    acc[i][1] = fmaf(wv.x, xv1.x, acc[i][1]);
                    acc[i][1] = fmaf(wv.y, xv1.y, acc[i][1]);
                    acc[i][1] = fmaf(wv.z, xv1.z, acc[i][1]);
                    acc[i][1] = fmaf(wv.w, xv1.w, acc[i][1]);
                }
            }
        }
    }

    size_t bkL2 = (size_t)bk * (LL/2);
    float* bcF = (float*)g_BC4;
    float* bnF = (float*)g_Bn2;
    #pragma unroll
    for (int i = 0; i < 9; i++) {
        int c = cbase + 8*i;
        if (c < 70) {
            #pragma unroll
            for (int g = 0; g < 2; g++) {
                int l = l0 + 32*g + lane;
                int l2 = l >> 1, lb = l & 1;
                float v = acc[i][g];
                if (c < 6) {
                    g_dts[((size_t)bk*RR + c)*LL + l] = v;
                } else if (c < 38) {
                    int n = c - 6;
                    bcF[((bkL2 + l2)*NS + n)*4 + 2*lb] = v;
                    bnF[((bkL2 + l2)*NS + n)*2 + lb]   = v;
                } else {
                    int n = c - 38;
                    bcF[((bkL2 + l2)*NS + n)*4 + 2*lb + 1] = v;
                }
            }
        }
    }
}

// ===== K4: dt_proj + softplus, pack (delta,u); indices from gridDim =====
// grid (9, DI, BB*KK): l = bx*256+tid, d = by, bk = bz. No div/mod.
__global__ void __launch_bounds__(256) k4_delta(const float* __restrict__ dtw,
                                                const float* __restrict__ dtb) {
    int l  = blockIdx.x * 256 + threadIdx.x;
    int d  = blockIdx.y;
    int bk = blockIdx.z;
    int k = bk & 3, b = bk >> 2;
    const float* dts = g_dts + (size_t)bk*RR*LL + l;
    const float* wr  = dtw + (size_t)(k*DI + d)*RR;
    float xv = dtb[k*DI + d];
    #pragma unroll
    for (int r = 0; r < RR; r++) xv = fmaf(dts[(size_t)r*LL], wr[r], xv);
    float delta = (xv > 15.f) ? xv : __logf(1.f + __expf(xv));
    const float* xbase = (k & 1) ? g_xconvT : g_xconv;
    int midx = (k < 2) ? l : (LL - 1 - l);
    float u = xbase[((size_t)b*DI + d)*LL + midx];
    g_du[((size_t)bk*DI + d)*LL + l] = make_float2(delta, u);
}

// ===== K5a: pass 1 — per-chunk local scan: h_fin, decay P =====
__global__ void __launch_bounds__(128) k5a_pass1(const float* __restrict__ alog) {
    int warp = threadIdx.x >> 5;
    int lane = threadIdx.x & 31;
    int wid = blockIdx.x * 4 + warp;
    int ch  = blockIdx.y;
    int d = wid % DI;
    int k = (wid / DI) % KK;
    int b =  wid / (DI*KK);
    int bk = b*KK + k;
    float a = -__expf(alog[(size_t)(k*DI + d)*NS + lane]);
    const float4* du4 = (const float4*)(g_du + (size_t)wid * LL);
    const float2* bn2 = g_Bn2 + (size_t)bk*(LL/2)*NS + lane;
    float h = 0.f, S = 0.f;

    #pragma unroll 2
    for (int t = 0; t < CHL/8; t++) {
        int l0 = ch*CHL + t*8;
        int l2_0 = l0 >> 1;
        float4 dub[4];
        #pragma unroll
        for (int i = 0; i < 4; i++) dub[i] = du4[(l0 >> 1) + i];
        float2 bw[4];
        #pragma unroll
        for (int j = 0; j < 4; j++) bw[j] = bn2[(size_t)(l2_0 + j)*NS];
        float dl[8], ul[8], w[8], bv[8];
        #pragma unroll
        for (int i = 0; i < 4; i++) {
            dl[2*i]   = dub[i].x; ul[2*i]   = dub[i].y;
            dl[2*i+1] = dub[i].z; ul[2*i+1] = dub[i].w;
            bv[2*i]   = bw[i].x;  bv[2*i+1] = bw[i].y;
        }
        #pragma unroll
        for (int i = 0; i < 8; i++) w[i] = __expf(dl[i] * a);
        #pragma unroll
        for (int i = 0; i < 8; i++) {
            h = fmaf(h, w[i], (dl[i] * ul[i]) * bv[i]);
            S += dl[i];
        }
    }
    size_t o = ((size_t)wid * NCH + ch) * NS + lane;
    g_hfin[o] = h;
    g_P[o]    = __expf(a * S);
}

// ===== K5b: combine chunk states serially (trivial) =====
__global__ void __launch_bounds__(128) k5b_combine() {
    int wid = blockIdx.x * 4 + (threadIdx.x >> 5);
    int lane = threadIdx.x & 31;
    size_t base = (size_t)wid * NCH * NS + lane;
    float hin = 0.f;
    #pragma unroll
    for (int c = 0; c < NCH; c++) {
        g_hin[base + (size_t)c*NS] = hin;
        if (c < NCH-1)
            hin = fmaf(g_P[base + (size_t)c*NS], hin, g_hfin[base + (size_t)c*NS]);
    }
}

// ===== K5c: pass 2 — full scan per chunk from h_in, y output =====
__global__ void __launch_bounds__(128) k5c_pass2(const float* __restrict__ alog,
                                                 const float* __restrict__ dsv) {
    int warp = threadIdx.x >> 5;
    int lane = threadIdx.x & 31;
    int wid = blockIdx.x * 4 + warp;
    int ch  = blockIdx.y;
    int d = wid % DI;
    int k = (wid / DI) % KK;
    int b =  wid / (DI*KK);
    int bk = b*KK + k;
    float a = -__expf(alog[(size_t)(k*DI + d)*NS + lane]);
    float dk0 = (lane == 0) ? dsv[k*DI + d] : 0.f;
    const float4* du4 = (const float4*)(g_du + (size_t)wid * LL);
    const float4* bc4 = g_BC4 + (size_t)bk*(LL/2)*NS + lane;
    float* yo = g_y + ((size_t)bk*LL)*DI + d;
    float h = g_hin[((size_t)wid * NCH + ch) * NS + lane];

    #pragma unroll 2
    for (int t = 0; t < CHL/8; t++) {
        int l0 = ch*CHL + t*8;
        int l2_0 = l0 >> 1;
        float4 dub[4];
        #pragma unroll
        for (int i = 0; i < 4; i++) dub[i] = du4[(l0 >> 1) + i];
        float4 bq[4];
        #pragma unroll
        for (int j = 0; j < 4; j++) bq[j] = bc4[(size_t)(l2_0 + j)*NS];
        float dl[8], ul[8], w[8], bb[8], cc[8];
        #pragma unroll
        for (int i = 0; i < 4; i++) {
            dl[2*i]   = dub[i].x; ul[2*i]   = dub[i].y;
            dl[2*i+1] = dub[i].z; ul[2*i+1] = dub[i].w;
            bb[2*i]   = bq[i].x;  cc[2*i]   = bq[i].y;
            bb[2*i+1] = bq[i].z;  cc[2*i+1] = bq[i].w;
        }
        #pragma unroll
        for (int i = 0; i < 8; i++) w[i] = __expf(dl[i] * a);

        float p[8];
        #pragma unroll
        for (int i = 0; i < 8; i++) {
            h = fmaf(h, w[i], (dl[i] * ul[i]) * bb[i]);
            p[i] = fmaf(dk0, ul[i], h * cc[i]);
        }

        // value-halving multi-reduction: 9 shfls for 8 sums
        {
            bool hi = (lane & 16) != 0;
            #pragma unroll
            for (int i = 0; i < 4; i++) {
                float send = hi ? p[i] : p[i+4];
                float keep = hi ? p[i+4] : p[i];
                p[i] = keep + __shfl_xor_sync(0xffffffffu, send, 16);
            }
        }
        {
            bool hi = (lane & 8) != 0;
            #pragma unroll
            for (int i = 0; i < 2; i++) {
                float send = hi ? p[i] : p[i+2];
                float keep = hi ? p[i+2] : p[i];
                p[i] = keep + __shfl_xor_sync(0xffffffffu, send, 8);
            }
        }
        {
            bool hi = (lane & 4) != 0;
            float send = hi ? p[0] : p[1];
            float keep = hi ? p[1] : p[0];
            p[0] = keep + __shfl_xor_sync(0xffffffffu, send, 4);
        }
        p[0] += __shfl_xor_sync(0xffffffffu, p[0], 2);
        p[0] += __shfl_xor_sync(0xffffffffu, p[0], 1);
        if ((lane & 3) == 0) yo[(size_t)(l0 + (lane >> 2)) * DI] = p[0];
    }
}

// ================= K6: combine dirs + LN + gate + out_proj + residual =====
__global__ void __launch_bounds__(192) k6_out(const float* __restrict__ x,
                                              const float* __restrict__ lnw,
                                              const float* __restrict__ lnb,
                                              float* __restrict__ out) {
    __shared__ float sy[DI];
    __shared__ float part8[8][CC];
    __shared__ float rs[6], rq[6];
    int b = blockIdx.x / LL, p = blockIdx.x % LL;
    int h = p / WW, w = p % WW;
    int l1 = w * HH + h;
    int d = threadIdx.x;
    size_t base = (size_t)b * KK * LL * DI;
    float y = g_y[base + ((size_t)0*LL + p)           *DI + d]
            + g_y[base + ((size_t)2*LL + (LL-1-p))    *DI + d]
            + g_y[base + ((size_t)1*LL + l1)          *DI + d]
            + g_y[base + ((size_t)3*LL + (LL-1-l1))   *DI + d];
    float s1 = y, s2 = y*y;
    #pragma unroll
    for (int o = 16; o; o >>= 1) {
        s1 += __shfl_xor_sync(0xffffffffu, s1, o);
        s2 += __shfl_xor_sync(0xffffffffu, s2, o);
    }
    int lane = d & 31, wd = d >> 5;
    if (lane == 0) { rs[wd] = s1; rq[wd] = s2; }
    __syncthreads();
    float tot = 0.f, totq = 0.f;
    #pragma unroll
    for (int i = 0; i < 6; i++) { tot += rs[i]; totq += rq[i]; }
    float mu  = tot  * (1.f/DI);
    float var = totq * (1.f/DI) - mu*mu;
    float inv = rsqrtf(var + 1e-5f);
    float yn = (y - mu) * inv * lnw[d] + lnb[d];
    yn *= g_z[((size_t)b*LL + p)*DI + d];
    sy[d] = yn;
    __syncthreads();

    int q = d / 24, m = d % 24;
    const float4* wt = (const float4*)g_opwT + (size_t)q*24*24 + m;
    float4 acc = make_float4(0.f, 0.f, 0.f, 0.f);
    #pragma unroll 6
    for (int j = 0; j < 24; j++) {
        float sv = sy[q*24 + j];
        float4 wv = wt[(size_t)j*24];
        acc.x = fmaf(wv.x, sv, acc.x);
        acc.y = fmaf(wv.y, sv, acc.y);
        acc.z = fmaf(wv.z, sv, acc.z);
        acc.w = fmaf(wv.w, sv, acc.w);
    }
    *(float4*)&part8[q][4*m] = acc;
    __syncthreads();
    if (d < CC) {
        float s = 0.f;
        #pragma unroll
        for (int i = 0; i < 8; i++) s += part8[i][d];
        size_t o = ((size_t)b*LL + p)*CC + d;
        out[o] = x[o] + s;
    }
}

extern "C" void kernel_launch(void* const* d_in, const int* in_sizes, int n_in,
                              void* d_out, int out_size) {
    const float* x    = (const float*)d_in[0];
    const float* ipw  = (const float*)d_in[1];
    const float* cw   = (const float*)d_in[2];
    const float* cb   = (const float*)d_in[3];
    const float* xpw  = (const float*)d_in[4];
    const float* dtw  = (const float*)d_in[5];
    const float* dtb  = (const float*)d_in[6];
    const float* alog = (const float*)d_in[7];
    const float* dsv  = (const float*)d_in[8];
    const float* lnw  = (const float*)d_in[9];
    const float* lnb  = (const float*)d_in[10];
    const float* opw  = (const float*)d_in[11];
    float* out = (float*)d_out;

    k0_transpose<<<(DI*CC + 255)/256, 256>>>(opw);

    dim3 g1(BB * (LL/32), 8);
    k1_inproj<<<g1, 256>>>(x, ipw);

    k2_conv<<<BB*DI, 256>>>(cw, cb);

    dim3 g3(LL/L3, BB*KK);
    k3_xproj<<<g3, 256>>>(xpw);

    dim3 g4(LL/256, DI, BB*KK);
    k4_delta<<<g4, 256>>>(dtw, dtb);

    dim3 gs1(BB*KK*DI/4, NCH-1);
    k5a_pass1<<<gs1, 128>>>(alog);
    k5b_combine<<<BB*KK*DI/128, 128>>>();
    dim3 gs2(BB*KK*DI/4, NCH);
    k5c_pass2<<<gs2, 128>>>(alog, dsv);

    k6_out<<<BB*LL, 192>>>(x, lnw, lnb, out);

    (void)in_sizes; (void)n_in; (void)out_size;
}

// round 14
// speedup vs baseline: 1.4088x; 1.4088x over previous
#include <cuda_runtime.h>
#include <cstdint>

#define BB 2
#define HH 48
#define WW 48
#define CC 96
#define LL (HH*WW)        // 2304
#define DI 192
#define NS 32
#define RR 6
#define KK 4
#define NCH 6
#define CHL (LL/NCH)      // 384

// ---- scratch (device globals; no allocations allowed) ----
__device__ float  g_xraw  [BB*DI*LL];
__device__ float  g_xconv [BB*DI*LL];          // conv+silu, hw-order (b,d,l)
__device__ float  g_xconvT[BB*DI*LL];          // conv+silu, wh-order (b,d,j)
__device__ float  g_z     [BB*LL*DI];          // silu(z), (b,l,d)
__device__ float  g_dts   [BB*KK*RR*LL];       // (b,k,r,l)
__device__ float4 g_BC4   [BB*KK*(LL/2)*NS];   // (b,k,l/2,n) -> (B0,C0,B1,C1)
__device__ float2 g_Bn2   [BB*KK*(LL/2)*NS];   // (b,k,l/2,n) -> (B0,B1)
__device__ float2 g_du    [BB*KK*DI*LL];       // (delta,u) per (b,k,d,l)
__device__ float  g_y     [(size_t)BB*KK*LL*DI];
__device__ float  g_hfin  [BB*KK*DI*NCH*NS];
__device__ float  g_P     [BB*KK*DI*NCH*NS];
__device__ float  g_hin   [BB*KK*DI*NCH*NS];
__device__ float  g_opwT  [DI*CC];             // transposed out_proj [d][c]

// ===== K0: transpose out_proj weight (tiny, once per launch) =====
__global__ void __launch_bounds__(256) k0_transpose(const float* __restrict__ opw) {
    int idx = blockIdx.x * 256 + threadIdx.x;
    if (idx >= DI*CC) return;
    int d = idx / CC, c = idx % CC;
    g_opwT[idx] = opw[(size_t)c*DI + d];
}

// ================= K1: in_proj + split + silu(z) =================
__global__ void __launch_bounds__(256, 4) k1_inproj(const float* __restrict__ x,
                                                    const float* __restrict__ ipw) {
    __shared__ float sm[32][97];
    int bl = blockIdx.x;
    int lt = bl % (LL/32), b = bl / (LL/32);
    int l0 = lt * 32;
    int tid = threadIdx.x, lane = tid & 31, wid = tid >> 5;
    for (int i = tid; i < 32*96; i += 256) {
        int j = i / 96, c = i % 96;
        sm[j][c] = x[((size_t)b*LL + l0 + j)*CC + c];
    }
    __syncthreads();
    int e0 = (blockIdx.y * 8 + wid) * 6;
    float acc[6] = {0.f,0.f,0.f,0.f,0.f,0.f};
    #pragma unroll 4
    for (int c4 = 0; c4 < 24; c4++) {
        float s0 = sm[lane][c4*4+0], s1 = sm[lane][c4*4+1];
        float s2 = sm[lane][c4*4+2], s3 = sm[lane][c4*4+3];
        #pragma unroll
        for (int i = 0; i < 6; i++) {
            const float4 wv = *(const float4*)(ipw + (size_t)(e0+i)*CC + c4*4);
            acc[i] = fmaf(wv.x, s0, acc[i]);
            acc[i] = fmaf(wv.y, s1, acc[i]);
            acc[i] = fmaf(wv.z, s2, acc[i]);
            acc[i] = fmaf(wv.w, s3, acc[i]);
        }
    }
    int l = l0 + lane;
    #pragma unroll
    for (int i = 0; i < 6; i++) {
        int e = e0 + i;
        if (e < DI) {
            g_xraw[((size_t)b*DI + e)*LL + l] = acc[i];
        } else {
            float v = acc[i];
            g_z[((size_t)b*LL + l)*DI + (e - DI)] = v / (1.f + __expf(-v));
        }
    }
}

// ===== K2: depthwise conv 3x3 + bias + silu; writes hw AND wh layouts =====
__global__ void __launch_bounds__(256) k2_conv(const float* __restrict__ cw,
                                               const float* __restrict__ cb) {
    __shared__ float si[LL];
    __shared__ float so[HH*49];
    int bd = blockIdx.x;                 // = b*DI + d
    int d = bd % DI;
    int tid = threadIdx.x;
    const float* src = g_xraw + (size_t)bd * LL;
    for (int i = tid; i < LL; i += 256) si[i] = src[i];
    float wts[9];
    #pragma unroll
    for (int j = 0; j < 9; j++) wts[j] = cw[d*9 + j];
    float bias = cb[d];
    __syncthreads();
    for (int l = tid; l < LL; l += 256) {
        int h = l / WW, w = l % WW;
        float acc = bias;
        #pragma unroll
        for (int dh = -1; dh <= 1; dh++) {
            #pragma unroll
            for (int dw = -1; dw <= 1; dw++) {
                int hh = h + dh, ww2 = w + dw;
                if (hh >= 0 && hh < HH && ww2 >= 0 && ww2 < WW)
                    acc = fmaf(si[hh*WW + ww2], wts[(dh+1)*3 + (dw+1)], acc);
            }
        }
        float v = acc / (1.f + __expf(-acc));
        g_xconv[(size_t)bd*LL + l] = v;
        so[h*49 + w] = v;
    }
    __syncthreads();
    for (int j = tid; j < LL; j += 256) {     // j = w*HH + h
        int w = j / HH, h = j % HH;
        g_xconvT[(size_t)bd*LL + j] = so[h*49 + w];
    }
}

// ================= K3: x_proj (R9/R11 shape: 576 CTAs, 4/SM) =================
__global__ void __launch_bounds__(256, 4) k3_xproj(const float* __restrict__ xpw) {
    __shared__ float sm[96][32];
    int blk = blockIdx.x;
    int lt = blk % (LL/32);
    int bk = blk / (LL/32);
    int k = bk % KK, b = bk / KK;
    int l0 = lt * 32;
    int tid = threadIdx.x, lane = tid & 31, wid = tid >> 5;
    const float* xbase = (k & 1) ? g_xconvT : g_xconv;
    float acc[9];
    #pragma unroll
    for (int i = 0; i < 9; i++) acc[i] = 0.f;

    for (int pass = 0; pass < 2; pass++) {
        for (int i = tid; i < 96*32; i += 256) {
            int dd = i >> 5, j = i & 31;
            int l = l0 + j;
            int idx = (k < 2) ? l : (LL - 1 - l);
            sm[dd][j] = xbase[((size_t)b*DI + pass*96 + dd)*LL + idx];
        }
        __syncthreads();
        #pragma unroll 2
        for (int dd4 = 0; dd4 < 24; dd4++) {
            float s0 = sm[dd4*4+0][lane], s1 = sm[dd4*4+1][lane];
            float s2 = sm[dd4*4+2][lane], s3 = sm[dd4*4+3][lane];
            #pragma unroll
            for (int i = 0; i < 9; i++) {
                int c = wid + 8*i;
                if (c < 70) {
                    const float4 wv = *(const float4*)(xpw + ((size_t)(k*70 + c))*DI + pass*96 + dd4*4);
                    acc[i] = fmaf(wv.x, s0, acc[i]);
                    acc[i] = fmaf(wv.y, s1, acc[i]);
                    acc[i] = fmaf(wv.z, s2, acc[i]);
                    acc[i] = fmaf(wv.w, s3, acc[i]);
                }
            }
        }
        __syncthreads();
    }
    int l = l0 + lane;
    int l2 = l >> 1, lb = l & 1;
    size_t bkL2 = (size_t)bk * (LL/2);
    float* bcF = (float*)g_BC4;
    float* bnF = (float*)g_Bn2;
    #pragma unroll
    for (int i = 0; i < 9; i++) {
        int c = wid + 8*i;
        if (c < 70) {
            float v = acc[i];
            if (c < 6) {
                g_dts[((size_t)bk*RR + c)*LL + l] = v;
            } else if (c < 38) {
                int n = c - 6;
                bcF[((bkL2 + l2)*NS + n)*4 + 2*lb]     = v;
                bnF[((bkL2 + l2)*NS + n)*2 + lb]       = v;
            } else {
                int n = c - 38;
                bcF[((bkL2 + l2)*NS + n)*4 + 2*lb + 1] = v;
            }
        }
    }
}

// ===== K4: dt_proj + softplus, pack (delta,u) — block-uniform indexing =====
// Same linear grid/order as before; blockIdx.x = (bk*DI + d)*9 + lt, so all
// div/mod are block-uniform (UR path). Per-thread: l = lt*256 + tid only.
__global__ void __launch_bounds__(256) k4_delta(const float* __restrict__ dtw,
                                                const float* __restrict__ dtb) {
    int blk = blockIdx.x;
    int lt  = blk % (LL/256);            // 9 l-tiles
    int bkd = blk / (LL/256);
    int d   = bkd % DI;
    int bk  = bkd / DI;
    int k = bk & 3, b = bk >> 2;
    int l = lt * 256 + threadIdx.x;
    const float* dts = g_dts + (size_t)bk*RR*LL + l;
    const float* wr  = dtw + (size_t)(k*DI + d)*RR;
    float xv = dtb[k*DI + d];
    #pragma unroll
    for (int r = 0; r < RR; r++) xv = fmaf(dts[(size_t)r*LL], wr[r], xv);
    float delta = (xv > 15.f) ? xv : __logf(1.f + __expf(xv));
    const float* xbase = (k & 1) ? g_xconvT : g_xconv;
    int midx = (k < 2) ? l : (LL - 1 - l);
    float u = xbase[((size_t)b*DI + d)*LL + midx];
    g_du[((size_t)bk*DI + d)*LL + l] = make_float2(delta, u);
}

// ===== K5a: pass 1 — per-chunk local scan: h_fin, decay P =====
__global__ void __launch_bounds__(128) k5a_pass1(const float* __restrict__ alog) {
    int warp = threadIdx.x >> 5;
    int lane = threadIdx.x & 31;
    int wid = blockIdx.x * 4 + warp;
    int ch  = blockIdx.y;
    int d = wid % DI;
    int k = (wid / DI) % KK;
    int b =  wid / (DI*KK);
    int bk = b*KK + k;
    float a = -__expf(alog[(size_t)(k*DI + d)*NS + lane]);
    const float4* du4 = (const float4*)(g_du + (size_t)wid * LL);
    const float2* bn2 = g_Bn2 + (size_t)bk*(LL/2)*NS + lane;
    float h = 0.f, S = 0.f;

    #pragma unroll 2
    for (int t = 0; t < CHL/8; t++) {
        int l0 = ch*CHL + t*8;
        int l2_0 = l0 >> 1;
        float4 dub[4];
        #pragma unroll
        for (int i = 0; i < 4; i++) dub[i] = du4[(l0 >> 1) + i];
        float2 bw[4];
        #pragma unroll
        for (int j = 0; j < 4; j++) bw[j] = bn2[(size_t)(l2_0 + j)*NS];
        float dl[8], ul[8], w[8], bv[8];
        #pragma unroll
        for (int i = 0; i < 4; i++) {
            dl[2*i]   = dub[i].x; ul[2*i]   = dub[i].y;
            dl[2*i+1] = dub[i].z; ul[2*i+1] = dub[i].w;
            bv[2*i]   = bw[i].x;  bv[2*i+1] = bw[i].y;
        }
        #pragma unroll
        for (int i = 0; i < 8; i++) w[i] = __expf(dl[i] * a);
        #pragma unroll
        for (int i = 0; i < 8; i++) {
            h = fmaf(h, w[i], (dl[i] * ul[i]) * bv[i]);
            S += dl[i];
        }
    }
    size_t o = ((size_t)wid * NCH + ch) * NS + lane;
    g_hfin[o] = h;
    g_P[o]    = __expf(a * S);
}

// ===== K5b: combine chunk states serially (trivial) =====
__global__ void __launch_bounds__(128) k5b_combine() {
    int wid = blockIdx.x * 4 + (threadIdx.x >> 5);
    int lane = threadIdx.x & 31;
    size_t base = (size_t)wid * NCH * NS + lane;
    float hin = 0.f;
    #pragma unroll
    for (int c = 0; c < NCH; c++) {
        g_hin[base + (size_t)c*NS] = hin;
        if (c < NCH-1)
            hin = fmaf(g_P[base + (size_t)c*NS], hin, g_hfin[base + (size_t)c*NS]);
    }
}

// ===== K5c: pass 2 — full scan per chunk from h_in, y output =====
__global__ void __launch_bounds__(128) k5c_pass2(const float* __restrict__ alog,
                                                 const float* __restrict__ dsv) {
    int warp = threadIdx.x >> 5;
    int lane = threadIdx.x & 31;
    int wid = blockIdx.x * 4 + warp;
    int ch  = blockIdx.y;
    int d = wid % DI;
    int k = (wid / DI) % KK;
    int b =  wid / (DI*KK);
    int bk = b*KK + k;
    float a = -__expf(alog[(size_t)(k*DI + d)*NS + lane]);
    float dk0 = (lane == 0) ? dsv[k*DI + d] : 0.f;
    const float4* du4 = (const float4*)(g_du + (size_t)wid * LL);
    const float4* bc4 = g_BC4 + (size_t)bk*(LL/2)*NS + lane;
    float* yo = g_y + ((size_t)bk*LL)*DI + d;
    float h = g_hin[((size_t)wid * NCH + ch) * NS + lane];

    #pragma unroll 2
    for (int t = 0; t < CHL/8; t++) {
        int l0 = ch*CHL + t*8;
        int l2_0 = l0 >> 1;
        float4 dub[4];
        #pragma unroll
        for (int i = 0; i < 4; i++) dub[i] = du4[(l0 >> 1) + i];
        float4 bq[4];
        #pragma unroll
        for (int j = 0; j < 4; j++) bq[j] = bc4[(size_t)(l2_0 + j)*NS];
        float dl[8], ul[8], w[8], bb[8], cc[8];
        #pragma unroll
        for (int i = 0; i < 4; i++) {
            dl[2*i]   = dub[i].x; ul[2*i]   = dub[i].y;
            dl[2*i+1] = dub[i].z; ul[2*i+1] = dub[i].w;
            bb[2*i]   = bq[i].x;  cc[2*i]   = bq[i].y;
            bb[2*i+1] = bq[i].z;  cc[2*i+1] = bq[i].w;
        }
        #pragma unroll
        for (int i = 0; i < 8; i++) w[i] = __expf(dl[i] * a);

        float p[8];
        #pragma unroll
        for (int i = 0; i < 8; i++) {
            h = fmaf(h, w[i], (dl[i] * ul[i]) * bb[i]);
            p[i] = fmaf(dk0, ul[i], h * cc[i]);
        }

        // value-halving multi-reduction: 9 shfls for 8 sums
        {
            bool hi = (lane & 16) != 0;
            #pragma unroll
            for (int i = 0; i < 4; i++) {
                float send = hi ? p[i] : p[i+4];
                float keep = hi ? p[i+4] : p[i];
                p[i] = keep + __shfl_xor_sync(0xffffffffu, send, 16);
            }
        }
        {
            bool hi = (lane & 8) != 0;
            #pragma unroll
            for (int i = 0; i < 2; i++) {
                float send = hi ? p[i] : p[i+2];
                float keep = hi ? p[i+2] : p[i];
                p[i] = keep + __shfl_xor_sync(0xffffffffu, send, 8);
            }
        }
        {
            bool hi = (lane & 4) != 0;
            float send = hi ? p[0] : p[1];
            float keep = hi ? p[1] : p[0];
            p[0] = keep + __shfl_xor_sync(0xffffffffu, send, 4);
        }
        p[0] += __shfl_xor_sync(0xffffffffu, p[0], 2);
        p[0] += __shfl_xor_sync(0xffffffffu, p[0], 1);
        if ((lane & 3) == 0) yo[(size_t)(l0 + (lane >> 2)) * DI] = p[0];
    }
}

// ================= K6: combine dirs + LN + gate + out_proj + residual =====
__global__ void __launch_bounds__(192) k6_out(const float* __restrict__ x,
                                              const float* __restrict__ lnw,
                                              const float* __restrict__ lnb,
                                              float* __restrict__ out) {
    __shared__ float sy[DI];
    __shared__ float part8[8][CC];
    __shared__ float rs[6], rq[6];
    int b = blockIdx.x / LL, p = blockIdx.x % LL;
    int h = p / WW, w = p % WW;
    int l1 = w * HH + h;
    int d = threadIdx.x;
    size_t base = (size_t)b * KK * LL * DI;
    float y = g_y[base + ((size_t)0*LL + p)           *DI + d]
            + g_y[base + ((size_t)2*LL + (LL-1-p))    *DI + d]
            + g_y[base + ((size_t)1*LL + l1)          *DI + d]
            + g_y[base + ((size_t)3*LL + (LL-1-l1))   *DI + d];
    float s1 = y, s2 = y*y;
    #pragma unroll
    for (int o = 16; o; o >>= 1) {
        s1 += __shfl_xor_sync(0xffffffffu, s1, o);
        s2 += __shfl_xor_sync(0xffffffffu, s2, o);
    }
    int lane = d & 31, wd = d >> 5;
    if (lane == 0) { rs[wd] = s1; rq[wd] = s2; }
    __syncthreads();
    float tot = 0.f, totq = 0.f;
    #pragma unroll
    for (int i = 0; i < 6; i++) { tot += rs[i]; totq += rq[i]; }
    float mu  = tot  * (1.f/DI);
    float var = totq * (1.f/DI) - mu*mu;
    float inv = rsqrtf(var + 1e-5f);
    float yn = (y - mu) * inv * lnw[d] + lnb[d];
    yn *= g_z[((size_t)b*LL + p)*DI + d];
    sy[d] = yn;
    __syncthreads();

    int q = d / 24, m = d % 24;
    const float4* wt = (const float4*)g_opwT + (size_t)q*24*24 + m;
    float4 acc = make_float4(0.f, 0.f, 0.f, 0.f);
    #pragma unroll 6
    for (int j = 0; j < 24; j++) {
        float sv = sy[q*24 + j];
        float4 wv = wt[(size_t)j*24];
        acc.x = fmaf(wv.x, sv, acc.x);
        acc.y = fmaf(wv.y, sv, acc.y);
        acc.z = fmaf(wv.z, sv, acc.z);
        acc.w = fmaf(wv.w, sv, acc.w);
    }
    *(float4*)&part8[q][4*m] = acc;
    __syncthreads();
    if (d < CC) {
        float s = 0.f;
        #pragma unroll
        for (int i = 0; i < 8; i++) s += part8[i][d];
        size_t o = ((size_t)b*LL + p)*CC + d;
        out[o] = x[o] + s;
    }
}

extern "C" void kernel_launch(void* const* d_in, const int* in_sizes, int n_in,
                              void* d_out, int out_size) {
    const float* x    = (const float*)d_in[0];
    const float* ipw  = (const float*)d_in[1];
    const float* cw   = (const float*)d_in[2];
    const float* cb   = (const float*)d_in[3];
    const float* xpw  = (const float*)d_in[4];
    const float* dtw  = (const float*)d_in[5];
    const float* dtb  = (const float*)d_in[6];
    const float* alog = (const float*)d_in[7];
    const float* dsv  = (const float*)d_in[8];
    const float* lnw  = (const float*)d_in[9];
    const float* lnb  = (const float*)d_in[10];
    const float* opw  = (const float*)d_in[11];
    float* out = (float*)d_out;

    k0_transpose<<<(DI*CC + 255)/256, 256>>>(opw);

    dim3 g1(BB * (LL/32), 8);
    k1_inproj<<<g1, 256>>>(x, ipw);

    k2_conv<<<BB*DI, 256>>>(cw, cb);

    k3_xproj<<<BB*KK*(LL/32), 256>>>(xpw);

    k4_delta<<<BB*KK*DI*(LL/256), 256>>>(dtw, dtb);

    dim3 gs1(BB*KK*DI/4, NCH-1);
    k5a_pass1<<<gs1, 128>>>(alog);
    k5b_combine<<<BB*KK*DI/128, 128>>>();
    dim3 gs2(BB*KK*DI/4, NCH);
    k5c_pass2<<<gs2, 128>>>(alog, dsv);

    k6_out<<<BB*LL, 192>>>(x, lnw, lnb, out);

    (void)in_sizes; (void)n_in; (void)out_size;
}

// round 15
// speedup vs baseline: 1.4613x; 1.0373x over previous
#include <cuda_runtime.h>
#include <cstdint>

#define BB 2
#define HH 48
#define WW 48
#define CC 96
#define LL (HH*WW)        // 2304
#define DI 192
#define NS 32
#define RR 6
#define KK 4
#define NCH 6
#define CHL (LL/NCH)      // 384

// ---- scratch (device globals; no allocations allowed) ----
__device__ float  g_xraw  [BB*DI*LL];
__device__ float  g_xconv [BB*DI*LL];          // conv+silu, hw-order (b,d,l)
__device__ float  g_xconvT[BB*DI*LL];          // conv+silu, wh-order (b,d,j)
__device__ float  g_z     [BB*LL*DI];          // silu(z), (b,l,d)
__device__ float  g_dts   [BB*KK*RR*LL];       // (b,k,r,l)
__device__ float4 g_BC4   [BB*KK*(LL/2)*NS];   // (b,k,l/2,n) -> (B0,C0,B1,C1)
__device__ float2 g_Bn2   [BB*KK*(LL/2)*NS];   // (b,k,l/2,n) -> (B0,B1)
__device__ float2 g_du    [BB*KK*DI*LL];       // (delta,u) per (b,k,d,l)
__device__ float  g_y     [(size_t)BB*KK*LL*DI];
__device__ float  g_hfin  [BB*KK*DI*NCH*NS];
__device__ float  g_P     [BB*KK*DI*NCH*NS];
__device__ float  g_hin   [BB*KK*DI*NCH*NS];
__device__ float  g_opwT  [DI*CC];             // transposed out_proj [d][c]

// ===== K0: transpose out_proj weight (tiny, once per launch) =====
__global__ void __launch_bounds__(256) k0_transpose(const float* __restrict__ opw) {
    int idx = blockIdx.x * 256 + threadIdx.x;
    if (idx >= DI*CC) return;
    int d = idx / CC, c = idx % CC;
    g_opwT[idx] = opw[(size_t)c*DI + d];
}

// ================= K1: in_proj + split + silu(z) =================
__global__ void __launch_bounds__(256, 4) k1_inproj(const float* __restrict__ x,
                                                    const float* __restrict__ ipw) {
    __shared__ float sm[32][97];
    int bl = blockIdx.x;
    int lt = bl % (LL/32), b = bl / (LL/32);
    int l0 = lt * 32;
    int tid = threadIdx.x, lane = tid & 31, wid = tid >> 5;
    for (int i = tid; i < 32*96; i += 256) {
        int j = i / 96, c = i % 96;
        sm[j][c] = x[((size_t)b*LL + l0 + j)*CC + c];
    }
    __syncthreads();
    int e0 = (blockIdx.y * 8 + wid) * 6;
    float acc[6] = {0.f,0.f,0.f,0.f,0.f,0.f};
    #pragma unroll 4
    for (int c4 = 0; c4 < 24; c4++) {
        float s0 = sm[lane][c4*4+0], s1 = sm[lane][c4*4+1];
        float s2 = sm[lane][c4*4+2], s3 = sm[lane][c4*4+3];
        #pragma unroll
        for (int i = 0; i < 6; i++) {
            const float4 wv = *(const float4*)(ipw + (size_t)(e0+i)*CC + c4*4);
            acc[i] = fmaf(wv.x, s0, acc[i]);
            acc[i] = fmaf(wv.y, s1, acc[i]);
            acc[i] = fmaf(wv.z, s2, acc[i]);
            acc[i] = fmaf(wv.w, s3, acc[i]);
        }
    }
    int l = l0 + lane;
    #pragma unroll
    for (int i = 0; i < 6; i++) {
        int e = e0 + i;
        if (e < DI) {
            g_xraw[((size_t)b*DI + e)*LL + l] = acc[i];
        } else {
            float v = acc[i];
            g_z[((size_t)b*LL + l)*DI + (e - DI)] = v / (1.f + __expf(-v));
        }
    }
}

// ===== K2: depthwise conv 3x3 + bias + silu; writes hw AND wh layouts =====
__global__ void __launch_bounds__(256) k2_conv(const float* __restrict__ cw,
                                               const float* __restrict__ cb) {
    __shared__ float si[LL];
    __shared__ float so[HH*49];
    int bd = blockIdx.x;                 // = b*DI + d
    int d = bd % DI;
    int tid = threadIdx.x;
    const float* src = g_xraw + (size_t)bd * LL;
    for (int i = tid; i < LL; i += 256) si[i] = src[i];
    float wts[9];
    #pragma unroll
    for (int j = 0; j < 9; j++) wts[j] = cw[d*9 + j];
    float bias = cb[d];
    __syncthreads();
    for (int l = tid; l < LL; l += 256) {
        int h = l / WW, w = l % WW;
        float acc = bias;
        #pragma unroll
        for (int dh = -1; dh <= 1; dh++) {
            #pragma unroll
            for (int dw = -1; dw <= 1; dw++) {
                int hh = h + dh, ww2 = w + dw;
                if (hh >= 0 && hh < HH && ww2 >= 0 && ww2 < WW)
                    acc = fmaf(si[hh*WW + ww2], wts[(dh+1)*3 + (dw+1)], acc);
            }
        }
        float v = acc / (1.f + __expf(-acc));
        g_xconv[(size_t)bd*LL + l] = v;
        so[h*49 + w] = v;
    }
    __syncthreads();
    for (int j = tid; j < LL; j += 256) {     // j = w*HH + h
        int w = j / HH, h = j % HH;
        g_xconvT[(size_t)bd*LL + j] = so[h*49 + w];
    }
}

// ======== K3: x_proj, 576 CTAs 4/SM — weights staged in shared memory =======
// Per pass: 26.25KB weight slice copied coalesced into smem; hot-loop weight
// reads become LDS.128 broadcasts (1 wavefront vs ~4 for uniform LDG.128).
__global__ void __launch_bounds__(256, 4) k3_xproj(const float* __restrict__ xpw) {
    __shared__ float sm[96][32];
    __shared__ float sw[70*96];
    int blk = blockIdx.x;
    int lt = blk % (LL/32);
    int bk = blk / (LL/32);
    int k = bk % KK, b = bk / KK;
    int l0 = lt * 32;
    int tid = threadIdx.x, lane = tid & 31, wid = tid >> 5;
    const float* xbase = (k & 1) ? g_xconvT : g_xconv;
    const float4* xpw4 = (const float4*)xpw;   // DI = 48 float4 per c-row
    float4* sw4 = (float4*)sw;
    float acc[9];
    #pragma unroll
    for (int i = 0; i < 9; i++) acc[i] = 0.f;

    for (int pass = 0; pass < 2; pass++) {
        __syncthreads();                       // protect prior pass's smem
        // stage X tile (96 d x 32 l)
        for (int i = tid; i < 96*32; i += 256) {
            int dd = i >> 5, j = i & 31;
            int l = l0 + j;
            int idx = (k < 2) ? l : (LL - 1 - l);
            sm[dd][j] = xbase[((size_t)b*DI + pass*96 + dd)*LL + idx];
        }
        // stage weight slice (70 c x 96 d) as float4
        for (int t = tid; t < 70*24; t += 256) {
            int c = t / 24, q = t - c*24;
            sw4[c*24 + q] = xpw4[(size_t)(k*70 + c)*48 + pass*24 + q];
        }
        __syncthreads();
        #pragma unroll 2
        for (int dd4 = 0; dd4 < 24; dd4++) {
            float s0 = sm[dd4*4+0][lane], s1 = sm[dd4*4+1][lane];
            float s2 = sm[dd4*4+2][lane], s3 = sm[dd4*4+3][lane];
            #pragma unroll
            for (int i = 0; i < 9; i++) {
                int c = wid + 8*i;
                if (c < 70) {
                    float4 wv = *(const float4*)&sw[c*96 + dd4*4];
                    acc[i] = fmaf(wv.x, s0, acc[i]);
                    acc[i] = fmaf(wv.y, s1, acc[i]);
                    acc[i] = fmaf(wv.z, s2, acc[i]);
                    acc[i] = fmaf(wv.w, s3, acc[i]);
                }
            }
        }
    }
    int l = l0 + lane;
    int l2 = l >> 1, lb = l & 1;
    size_t bkL2 = (size_t)bk * (LL/2);
    float* bcF = (float*)g_BC4;
    float* bnF = (float*)g_Bn2;
    #pragma unroll
    for (int i = 0; i < 9; i++) {
        int c = wid + 8*i;
        if (c < 70) {
            float v = acc[i];
            if (c < 6) {
                g_dts[((size_t)bk*RR + c)*LL + l] = v;
            } else if (c < 38) {
                int n = c - 6;
                bcF[((bkL2 + l2)*NS + n)*4 + 2*lb]     = v;
                bnF[((bkL2 + l2)*NS + n)*2 + lb]       = v;
            } else {
                int n = c - 38;
                bcF[((bkL2 + l2)*NS + n)*4 + 2*lb + 1] = v;
            }
        }
    }
}

// ================= K4: dt_proj + softplus, pack (delta,u) =================
__global__ void __launch_bounds__(256) k4_delta(const float* __restrict__ dtw,
                                                const float* __restrict__ dtb) {
    int idx = blockIdx.x * 256 + threadIdx.x;
    if (idx >= BB*KK*DI*LL) return;
    int l = idx % LL;
    int d = (idx / LL) % DI;
    int k = (idx / (LL*DI)) % KK;
    int b =  idx / (LL*DI*KK);
    int bk = b*KK + k;
    const float* dts = g_dts + (size_t)bk*RR*LL + l;
    const float* wr  = dtw + (size_t)(k*DI + d)*RR;
    float xv = dtb[k*DI + d];
    #pragma unroll
    for (int r = 0; r < RR; r++) xv = fmaf(dts[(size_t)r*LL], wr[r], xv);
    float delta = (xv > 15.f) ? xv : __logf(1.f + __expf(xv));
    const float* xbase = (k & 1) ? g_xconvT : g_xconv;
    int midx = (k < 2) ? l : (LL - 1 - l);
    float u = xbase[((size_t)b*DI + d)*LL + midx];
    g_du[idx] = make_float2(delta, u);
}

// ===== K5a: pass 1 — per-chunk local scan: h_fin, decay P =====
__global__ void __launch_bounds__(128) k5a_pass1(const float* __restrict__ alog) {
    int warp = threadIdx.x >> 5;
    int lane = threadIdx.x & 31;
    int wid = blockIdx.x * 4 + warp;
    int ch  = blockIdx.y;
    int d = wid % DI;
    int k = (wid / DI) % KK;
    int b =  wid / (DI*KK);
    int bk = b*KK + k;
    float a = -__expf(alog[(size_t)(k*DI + d)*NS + lane]);
    const float4* du4 = (const float4*)(g_du + (size_t)wid * LL);
    const float2* bn2 = g_Bn2 + (size_t)bk*(LL/2)*NS + lane;
    float h = 0.f, S = 0.f;

    #pragma unroll 2
    for (int t = 0; t < CHL/8; t++) {
        int l0 = ch*CHL + t*8;
        int l2_0 = l0 >> 1;
        float4 dub[4];
        #pragma unroll
        for (int i = 0; i < 4; i++) dub[i] = du4[(l0 >> 1) + i];
        float2 bw[4];
        #pragma unroll
        for (int j = 0; j < 4; j++) bw[j] = bn2[(size_t)(l2_0 + j)*NS];
        float dl[8], ul[8], w[8], bv[8];
        #pragma unroll
        for (int i = 0; i < 4; i++) {
            dl[2*i]   = dub[i].x; ul[2*i]   = dub[i].y;
            dl[2*i+1] = dub[i].z; ul[2*i+1] = dub[i].w;
            bv[2*i]   = bw[i].x;  bv[2*i+1] = bw[i].y;
        }
        #pragma unroll
        for (int i = 0; i < 8; i++) w[i] = __expf(dl[i] * a);
        #pragma unroll
        for (int i = 0; i < 8; i++) {
            h = fmaf(h, w[i], (dl[i] * ul[i]) * bv[i]);
            S += dl[i];
        }
    }
    size_t o = ((size_t)wid * NCH + ch) * NS + lane;
    g_hfin[o] = h;
    g_P[o]    = __expf(a * S);
}

// ===== K5b: combine chunk states serially (trivial) =====
__global__ void __launch_bounds__(128) k5b_combine() {
    int wid = blockIdx.x * 4 + (threadIdx.x >> 5);
    int lane = threadIdx.x & 31;
    size_t base = (size_t)wid * NCH * NS + lane;
    float hin = 0.f;
    #pragma unroll
    for (int c = 0; c < NCH; c++) {
        g_hin[base + (size_t)c*NS] = hin;
        if (c < NCH-1)
            hin = fmaf(g_P[base + (size_t)c*NS], hin, g_hfin[base + (size_t)c*NS]);
    }
}

// ===== K5c: pass 2 — full scan per chunk from h_in, y output =====
__global__ void __launch_bounds__(128) k5c_pass2(const float* __restrict__ alog,
                                                 const float* __restrict__ dsv) {
    int warp = threadIdx.x >> 5;
    int lane = threadIdx.x & 31;
    int wid = blockIdx.x * 4 + warp;
    int ch  = blockIdx.y;
    int d = wid % DI;
    int k = (wid / DI) % KK;
    int b =  wid / (DI*KK);
    int bk = b*KK + k;
    float a = -__expf(alog[(size_t)(k*DI + d)*NS + lane]);
    float dk0 = (lane == 0) ? dsv[k*DI + d] : 0.f;
    const float4* du4 = (const float4*)(g_du + (size_t)wid * LL);
    const float4* bc4 = g_BC4 + (size_t)bk*(LL/2)*NS + lane;
    float* yo = g_y + ((size_t)bk*LL)*DI + d;
    float h = g_hin[((size_t)wid * NCH + ch) * NS + lane];

    #pragma unroll 2
    for (int t = 0; t < CHL/8; t++) {
        int l0 = ch*CHL + t*8;
        int l2_0 = l0 >> 1;
        float4 dub[4];
        #pragma unroll
        for (int i = 0; i < 4; i++) dub[i] = du4[(l0 >> 1) + i];
        float4 bq[4];
        #pragma unroll
        for (int j = 0; j < 4; j++) bq[j] = bc4[(size_t)(l2_0 + j)*NS];
        float dl[8], ul[8], w[8], bb[8], cc[8];
        #pragma unroll
        for (int i = 0; i < 4; i++) {
            dl[2*i]   = dub[i].x; ul[2*i]   = dub[i].y;
            dl[2*i+1] = dub[i].z; ul[2*i+1] = dub[i].w;
            bb[2*i]   = bq[i].x;  cc[2*i]   = bq[i].y;
            bb[2*i+1] = bq[i].z;  cc[2*i+1] = bq[i].w;
        }
        #pragma unroll
        for (int i = 0; i < 8; i++) w[i] = __expf(dl[i] * a);

        float p[8];
        #pragma unroll
        for (int i = 0; i < 8; i++) {
            h = fmaf(h, w[i], (dl[i] * ul[i]) * bb[i]);
            p[i] = fmaf(dk0, ul[i], h * cc[i]);
        }

        // value-halving multi-reduction: 9 shfls for 8 sums
        {
            bool hi = (lane & 16) != 0;
            #pragma unroll
            for (int i = 0; i < 4; i++) {
                float send = hi ? p[i] : p[i+4];
                float keep = hi ? p[i+4] : p[i];
                p[i] = keep + __shfl_xor_sync(0xffffffffu, send, 16);
            }
        }
        {
            bool hi = (lane & 8) != 0;
            #pragma unroll
            for (int i = 0; i < 2; i++) {
                float send = hi ? p[i] : p[i+2];
                float keep = hi ? p[i+2] : p[i];
                p[i] = keep + __shfl_xor_sync(0xffffffffu, send, 8);
            }
        }
        {
            bool hi = (lane & 4) != 0;
            float send = hi ? p[0] : p[1];
            float keep = hi ? p[1] : p[0];
            p[0] = keep + __shfl_xor_sync(0xffffffffu, send, 4);
        }
        p[0] += __shfl_xor_sync(0xffffffffu, p[0], 2);
        p[0] += __shfl_xor_sync(0xffffffffu, p[0], 1);
        if ((lane & 3) == 0) yo[(size_t)(l0 + (lane >> 2)) * DI] = p[0];
    }
}

// ================= K6: combine dirs + LN + gate + out_proj + residual =====
__global__ void __launch_bounds__(192) k6_out(const float* __restrict__ x,
                                              const float* __restrict__ lnw,
                                              const float* __restrict__ lnb,
                                              float* __restrict__ out) {
    __shared__ float sy[DI];
    __shared__ float part8[8][CC];
    __shared__ float rs[6], rq[6];
    int b = blockIdx.x / LL, p = blockIdx.x % LL;
    int h = p / WW, w = p % WW;
    int l1 = w * HH + h;
    int d = threadIdx.x;
    size_t base = (size_t)b * KK * LL * DI;
    float y = g_y[base + ((size_t)0*LL + p)           *DI + d]
            + g_y[base + ((size_t)2*LL + (LL-1-p))    *DI + d]
            + g_y[base + ((size_t)1*LL + l1)          *DI + d]
            + g_y[base + ((size_t)3*LL + (LL-1-l1))   *DI + d];
    float s1 = y, s2 = y*y;
    #pragma unroll
    for (int o = 16; o; o >>= 1) {
        s1 += __shfl_xor_sync(0xffffffffu, s1, o);
        s2 += __shfl_xor_sync(0xffffffffu, s2, o);
    }
    int lane = d & 31, wd = d >> 5;
    if (lane == 0) { rs[wd] = s1; rq[wd] = s2; }
    __syncthreads();
    float tot = 0.f, totq = 0.f;
    #pragma unroll
    for (int i = 0; i < 6; i++) { tot += rs[i]; totq += rq[i]; }
    float mu  = tot  * (1.f/DI);
    float var = totq * (1.f/DI) - mu*mu;
    float inv = rsqrtf(var + 1e-5f);
    float yn = (y - mu) * inv * lnw[d] + lnb[d];
    yn *= g_z[((size_t)b*LL + p)*DI + d];
    sy[d] = yn;
    __syncthreads();

    int q = d / 24, m = d % 24;
    const float4* wt = (const float4*)g_opwT + (size_t)q*24*24 + m;
    float4 acc = make_float4(0.f, 0.f, 0.f, 0.f);
    #pragma unroll 6
    for (int j = 0; j < 24; j++) {
        float sv = sy[q*24 + j];
        float4 wv = wt[(size_t)j*24];
        acc.x = fmaf(wv.x, sv, acc.x);
        acc.y = fmaf(wv.y, sv, acc.y);
        acc.z = fmaf(wv.z, sv, acc.z);
        acc.w = fmaf(wv.w, sv, acc.w);
    }
    *(float4*)&part8[q][4*m] = acc;
    __syncthreads();
    if (d < CC) {
        float s = 0.f;
        #pragma unroll
        for (int i = 0; i < 8; i++) s += part8[i][d];
        size_t o = ((size_t)b*LL + p)*CC + d;
        out[o] = x[o] + s;
    }
}

extern "C" void kernel_launch(void* const* d_in, const int* in_sizes, int n_in,
                              void* d_out, int out_size) {
    const float* x    = (const float*)d_in[0];
    const float* ipw  = (const float*)d_in[1];
    const float* cw   = (const float*)d_in[2];
    const float* cb   = (const float*)d_in[3];
    const float* xpw  = (const float*)d_in[4];
    const float* dtw  = (const float*)d_in[5];
    const float* dtb  = (const float*)d_in[6];
    const float* alog = (const float*)d_in[7];
    const float* dsv  = (const float*)d_in[8];
    const float* lnw  = (const float*)d_in[9];
    const float* lnb  = (const float*)d_in[10];
    const float* opw  = (const float*)d_in[11];
    float* out = (float*)d_out;

    k0_transpose<<<(DI*CC + 255)/256, 256>>>(opw);

    dim3 g1(BB * (LL/32), 8);
    k1_inproj<<<g1, 256>>>(x, ipw);

    k2_conv<<<BB*DI, 256>>>(cw, cb);

    k3_xproj<<<BB*KK*(LL/32), 256>>>(xpw);

    k4_delta<<<(BB*KK*DI*LL + 255)/256, 256>>>(dtw, dtb);

    dim3 gs1(BB*KK*DI/4, NCH-1);
    k5a_pass1<<<gs1, 128>>>(alog);
    k5b_combine<<<BB*KK*DI/128, 128>>>();
    dim3 gs2(BB*KK*DI/4, NCH);
    k5c_pass2<<<gs2, 128>>>(alog, dsv);

    k6_out<<<BB*LL, 192>>>(x, lnw, lnb, out);

    (void)in_sizes; (void)n_in; (void)out_size;
}

// round 17
// speedup vs baseline: 1.5289x; 1.0463x over previous
#include <cuda_runtime.h>
#include <cstdint>

#define BB 2
#define HH 48
#define WW 48
#define CC 96
#define LL (HH*WW)        // 2304
#define DI 192
#define NS 32
#define RR 6
#define KK 4
#define NCH 6
#define CHL (LL/NCH)      // 384

__device__ __forceinline__ float ex2f(float x) {
    float r;
    asm("ex2.approx.f32 %0, %1;" : "=f"(r) : "f"(x));
    return r;
}
#define LOG2E 1.4426950408889634f

// ---- scratch (device globals; no allocations allowed) ----
__device__ float  g_xraw  [BB*DI*LL];
__device__ float  g_xconv [BB*DI*LL];          // conv+silu, hw-order (b,d,l)
__device__ float  g_xconvT[BB*DI*LL];          // conv+silu, wh-order (b,d,j)
__device__ float  g_z     [BB*LL*DI];          // silu(z), (b,l,d)
__device__ float  g_dts   [BB*KK*RR*LL];       // (b,k,r,l)
__device__ float4 g_BC4   [BB*KK*(LL/2)*NS];   // (b,k,l/2,n) -> (B0,C0,B1,C1)
__device__ float2 g_Bn2   [BB*KK*(LL/2)*NS];   // (b,k,l/2,n) -> (B0,B1)
__device__ float2 g_du    [BB*KK*DI*LL];       // (delta, delta*u) per (b,k,d,l)
__device__ float  g_y     [(size_t)BB*KK*LL*DI];
__device__ float  g_hfin  [BB*KK*DI*NCH*NS];
__device__ float  g_P     [BB*KK*DI*NCH*NS];
__device__ float  g_hin   [BB*KK*DI*NCH*NS];
__device__ float  g_opwT  [DI*CC];             // transposed out_proj [d][c]
__device__ float  g_sumD  [DI];                // sum_k Ds[k][d]

// ===== K0: transpose out_proj weight + sumD (tiny, once per launch) =====
__global__ void __launch_bounds__(256) k0_transpose(const float* __restrict__ opw,
                                                    const float* __restrict__ dsv) {
    int idx = blockIdx.x * 256 + threadIdx.x;
    if (idx < DI) {
        float s = 0.f;
        #pragma unroll
        for (int k = 0; k < KK; k++) s += dsv[k*DI + idx];
        g_sumD[idx] = s;
    }
    if (idx >= DI*CC) return;
    int d = idx / CC, c = idx % CC;
    g_opwT[idx] = opw[(size_t)c*DI + d];
}

// ================= K1: in_proj + split + silu(z) =================
__global__ void __launch_bounds__(256, 4) k1_inproj(const float* __restrict__ x,
                                                    const float* __restrict__ ipw) {
    __shared__ float sm[32][97];
    int bl = blockIdx.x;
    int lt = bl % (LL/32), b = bl / (LL/32);
    int l0 = lt * 32;
    int tid = threadIdx.x, lane = tid & 31, wid = tid >> 5;
    for (int i = tid; i < 32*96; i += 256) {
        int j = i / 96, c = i % 96;
        sm[j][c] = x[((size_t)b*LL + l0 + j)*CC + c];
    }
    __syncthreads();
    int e0 = (blockIdx.y * 8 + wid) * 6;
    float acc[6] = {0.f,0.f,0.f,0.f,0.f,0.f};
    #pragma unroll 4
    for (int c4 = 0; c4 < 24; c4++) {
        float s0 = sm[lane][c4*4+0], s1 = sm[lane][c4*4+1];
        float s2 = sm[lane][c4*4+2], s3 = sm[lane][c4*4+3];
        #pragma unroll
        for (int i = 0; i < 6; i++) {
            const float4 wv = *(const float4*)(ipw + (size_t)(e0+i)*CC + c4*4);
            acc[i] = fmaf(wv.x, s0, acc[i]);
            acc[i] = fmaf(wv.y, s1, acc[i]);
            acc[i] = fmaf(wv.z, s2, acc[i]);
            acc[i] = fmaf(wv.w, s3, acc[i]);
        }
    }
    int l = l0 + lane;
    #pragma unroll
    for (int i = 0; i < 6; i++) {
        int e = e0 + i;
        if (e < DI) {
            g_xraw[((size_t)b*DI + e)*LL + l] = acc[i];
        } else {
            float v = acc[i];
            g_z[((size_t)b*LL + l)*DI + (e - DI)] = v / (1.f + __expf(-v));
        }
    }
}

// ===== K2: depthwise conv 3x3 + bias + silu; writes hw AND wh layouts =====
__global__ void __launch_bounds__(256) k2_conv(const float* __restrict__ cw,
                                               const float* __restrict__ cb) {
    __shared__ float si[LL];
    __shared__ float so[HH*49];
    int bd = blockIdx.x;                 // = b*DI + d
    int d = bd % DI;
    int tid = threadIdx.x;
    const float* src = g_xraw + (size_t)bd * LL;
    for (int i = tid; i < LL; i += 256) si[i] = src[i];
    float wts[9];
    #pragma unroll
    for (int j = 0; j < 9; j++) wts[j] = cw[d*9 + j];
    float bias = cb[d];
    __syncthreads();
    for (int l = tid; l < LL; l += 256) {
        int h = l / WW, w = l % WW;
        float acc = bias;
        #pragma unroll
        for (int dh = -1; dh <= 1; dh++) {
            #pragma unroll
            for (int dw = -1; dw <= 1; dw++) {
                int hh = h + dh, ww2 = w + dw;
                if (hh >= 0 && hh < HH && ww2 >= 0 && ww2 < WW)
                    acc = fmaf(si[hh*WW + ww2], wts[(dh+1)*3 + (dw+1)], acc);
            }
        }
        float v = acc / (1.f + __expf(-acc));
        g_xconv[(size_t)bd*LL + l] = v;
        so[h*49 + w] = v;
    }
    __syncthreads();
    for (int j = tid; j < LL; j += 256) {     // j = w*HH + h
        int w = j / HH, h = j % HH;
        g_xconvT[(size_t)bd*LL + j] = so[h*49 + w];
    }
}

// ======== K3: x_proj, 576 CTAs 4/SM — weights staged in shared memory =======
__global__ void __launch_bounds__(256, 4) k3_xproj(const float* __restrict__ xpw) {
    __shared__ float sm[96][32];
    __shared__ float sw[70*96];
    int blk = blockIdx.x;
    int lt = blk % (LL/32);
    int bk = blk / (LL/32);
    int k = bk % KK, b = bk / KK;
    int l0 = lt * 32;
    int tid = threadIdx.x, lane = tid & 31, wid = tid >> 5;
    const float* xbase = (k & 1) ? g_xconvT : g_xconv;
    const float4* xpw4 = (const float4*)xpw;   // DI = 48 float4 per c-row
    float4* sw4 = (float4*)sw;
    float acc[9];
    #pragma unroll
    for (int i = 0; i < 9; i++) acc[i] = 0.f;

    for (int pass = 0; pass < 2; pass++) {
        __syncthreads();
        for (int i = tid; i < 96*32; i += 256) {
            int dd = i >> 5, j = i & 31;
            int l = l0 + j;
            int idx = (k < 2) ? l : (LL - 1 - l);
            sm[dd][j] = xbase[((size_t)b*DI + pass*96 + dd)*LL + idx];
        }
        for (int t = tid; t < 70*24; t += 256) {
            int c = t / 24, q = t - c*24;
            sw4[c*24 + q] = xpw4[(size_t)(k*70 + c)*48 + pass*24 + q];
        }
        __syncthreads();
        #pragma unroll 2
        for (int dd4 = 0; dd4 < 24; dd4++) {
            float s0 = sm[dd4*4+0][lane], s1 = sm[dd4*4+1][lane];
            float s2 = sm[dd4*4+2][lane], s3 = sm[dd4*4+3][lane];
            #pragma unroll
            for (int i = 0; i < 9; i++) {
                int c = wid + 8*i;
                if (c < 70) {
                    float4 wv = *(const float4*)&sw[c*96 + dd4*4];
                    acc[i] = fmaf(wv.x, s0, acc[i]);
                    acc[i] = fmaf(wv.y, s1, acc[i]);
                    acc[i] = fmaf(wv.z, s2, acc[i]);
                    acc[i] = fmaf(wv.w, s3, acc[i]);
                }
            }
        }
    }
    int l = l0 + lane;
    int l2 = l >> 1, lb = l & 1;
    size_t bkL2 = (size_t)bk * (LL/2);
    float* bcF = (float*)g_BC4;
    float* bnF = (float*)g_Bn2;
    #pragma unroll
    for (int i = 0; i < 9; i++) {
        int c = wid + 8*i;
        if (c < 70) {
            float v = acc[i];
            if (c < 6) {
                g_dts[((size_t)bk*RR + c)*LL + l] = v;
            } else if (c < 38) {
                int n = c - 6;
                bcF[((bkL2 + l2)*NS + n)*4 + 2*lb]     = v;
                bnF[((bkL2 + l2)*NS + n)*2 + lb]       = v;
            } else {
                int n = c - 38;
                bcF[((bkL2 + l2)*NS + n)*4 + 2*lb + 1] = v;
            }
        }
    }
}

// ===== K4: dt_proj + softplus, pack (delta, delta*u) =====
__global__ void __launch_bounds__(256) k4_delta(const float* __restrict__ dtw,
                                                const float* __restrict__ dtb) {
    int idx = blockIdx.x * 256 + threadIdx.x;
    if (idx >= BB*KK*DI*LL) return;
    int l = idx % LL;
    int d = (idx / LL) % DI;
    int k = (idx / (LL*DI)) % KK;
    int b =  idx / (LL*DI*KK);
    int bk = b*KK + k;
    const float* dts = g_dts + (size_t)bk*RR*LL + l;
    const float* wr  = dtw + (size_t)(k*DI + d)*RR;
    float xv = dtb[k*DI + d];
    #pragma unroll
    for (int r = 0; r < RR; r++) xv = fmaf(dts[(size_t)r*LL], wr[r], xv);
    float delta = (xv > 15.f) ? xv : __logf(1.f + __expf(xv));
    const float* xbase = (k & 1) ? g_xconvT : g_xconv;
    int midx = (k < 2) ? l : (LL - 1 - l);
    float u = xbase[((size_t)b*DI + d)*LL + midx];
    g_du[idx] = make_float2(delta, delta * u);
}

// ===== K5a: pass 1 — per-chunk local scan: h_fin, decay P =====
__global__ void __launch_bounds__(128) k5a_pass1(const float* __restrict__ alog) {
    int warp = threadIdx.x >> 5;
    int lane = threadIdx.x & 31;
    int wid = blockIdx.x * 4 + warp;
    int ch  = blockIdx.y;
    int d = wid % DI;
    int k = (wid / DI) % KK;
    int b =  wid / (DI*KK);
    int bk = b*KK + k;
    float a  = -__expf(alog[(size_t)(k*DI + d)*NS + lane]);
    float a2 = a * LOG2E;                 // exp(dl*a) == ex2(dl*a2)
    const float4* du4 = (const float4*)(g_du + (size_t)wid * LL);
    const float2* bn2 = g_Bn2 + (size_t)bk*(LL/2)*NS + lane;
    float h = 0.f, S = 0.f;

    #pragma unroll 2
    for (int t = 0; t < CHL/8; t++) {
        int l0 = ch*CHL + t*8;
        int l2_0 = l0 >> 1;
        float4 dub[4];
        #pragma unroll
        for (int i = 0; i < 4; i++) dub[i] = du4[(l0 >> 1) + i];
        float2 bw[4];
        #pragma unroll
        for (int j = 0; j < 4; j++) bw[j] = bn2[(size_t)(l2_0 + j)*NS];
        float dl[8], xu[8], w[8], bv[8];
        #pragma unroll
        for (int i = 0; i < 4; i++) {
            dl[2*i]   = dub[i].x; xu[2*i]   = dub[i].y;
            dl[2*i+1] = dub[i].z; xu[2*i+1] = dub[i].w;
            bv[2*i]   = bw[i].x;  bv[2*i+1] = bw[i].y;
        }
        #pragma unroll
        for (int i = 0; i < 8; i++) w[i] = ex2f(dl[i] * a2);
        #pragma unroll
        for (int i = 0; i < 8; i++) {
            h = fmaf(h, w[i], xu[i] * bv[i]);
            S += dl[i];
        }
    }
    size_t o = ((size_t)wid * NCH + ch) * NS + lane;
    g_hfin[o] = h;
    g_P[o]    = ex2f(a2 * S);
}

// ===== K5b: combine chunk states serially (trivial) =====
__global__ void __launch_bounds__(128) k5b_combine() {
    int wid = blockIdx.x * 4 + (threadIdx.x >> 5);
    int lane = threadIdx.x & 31;
    size_t base = (size_t)wid * NCH * NS + lane;
    float hin = 0.f;
    #pragma unroll
    for (int c = 0; c < NCH; c++) {
        g_hin[base + (size_t)c*NS] = hin;
        if (c < NCH-1)
            hin = fmaf(g_P[base + (size_t)c*NS], hin, g_hfin[base + (size_t)c*NS]);
    }
}

// ===== K5c: pass 2 — full scan per chunk from h_in, y output =====
__global__ void __launch_bounds__(128) k5c_pass2(const float* __restrict__ alog) {
    int warp = threadIdx.x >> 5;
    int lane = threadIdx.x & 31;
    int wid = blockIdx.x * 4 + warp;
    int ch  = blockIdx.y;
    int d = wid % DI;
    int k = (wid / DI) % KK;
    int b =  wid / (DI*KK);
    int bk = b*KK + k;
    float a  = -__expf(alog[(size_t)(k*DI + d)*NS + lane]);
    float a2 = a * LOG2E;
    const float4* du4 = (const float4*)(g_du + (size_t)wid * LL);
    const float4* bc4 = g_BC4 + (size_t)bk*(LL/2)*NS + lane;
    float* yo = g_y + ((size_t)bk*LL)*DI + d;
    float h = g_hin[((size_t)wid * NCH + ch) * NS + lane];

    #pragma unroll 2
    for (int t = 0; t < CHL/8; t++) {
        int l0 = ch*CHL + t*8;
        int l2_0 = l0 >> 1;
        float4 dub[4];
        #pragma unroll
        for (int i = 0; i < 4; i++) dub[i] = du4[(l0 >> 1) + i];
        float4 bq[4];
        #pragma unroll
        for (int j = 0; j < 4; j++) bq[j] = bc4[(size_t)(l2_0 + j)*NS];
        float dl[8], xu[8], w[8], bb[8], cc[8];
        #pragma unroll
        for (int i = 0; i < 4; i++) {
            dl[2*i]   = dub[i].x; xu[2*i]   = dub[i].y;
            dl[2*i+1] = dub[i].z; xu[2*i+1] = dub[i].w;
            bb[2*i]   = bq[i].x;  cc[2*i]   = bq[i].y;
            bb[2*i+1] = bq[i].z;  cc[2*i+1] = bq[i].w;
        }
        #pragma unroll
        for (int i = 0; i < 8; i++) w[i] = ex2f(dl[i] * a2);

        float p[8];
        #pragma unroll
        for (int i = 0; i < 8; i++) {
            h = fmaf(h, w[i], xu[i] * bb[i]);
            p[i] = h * cc[i];
        }

        // value-halving multi-reduction: 9 shfls for 8 sums
        {
            bool hi = (lane & 16) != 0;
            #pragma unroll
            for (int i = 0; i < 4; i++) {
                float send = hi ? p[i] : p[i+4];
                float keep = hi ? p[i+4] : p[i];
                p[i] = keep + __shfl_xor_sync(0xffffffffu, send, 16);
            }
        }
        {
            bool hi = (lane & 8) != 0;
            #pragma unroll
            for (int i = 0; i < 2; i++) {
                float send = hi ? p[i] : p[i+2];
                float keep = hi ? p[i+2] : p[i];
                p[i] = keep + __shfl_xor_sync(0xffffffffu, send, 8);
            }
        }
        {
            bool hi = (lane & 4) != 0;
            float send = hi ? p[0] : p[1];
            float keep = hi ? p[1] : p[0];
            p[0] = keep + __shfl_xor_sync(0xffffffffu, send, 4);
        }
        p[0] += __shfl_xor_sync(0xffffffffu, p[0], 2);
        p[0] += __shfl_xor_sync(0xffffffffu, p[0], 1);
        if ((lane & 3) == 0) yo[(size_t)(l0 + (lane >> 2)) * DI] = p[0];
    }
}

// ========= K6: combine dirs + D-skip + LN + gate + out_proj + residual =====
__global__ void __launch_bounds__(192) k6_out(const float* __restrict__ x,
                                              const float* __restrict__ lnw,
                                              const float* __restrict__ lnb,
                                              float* __restrict__ out) {
    __shared__ float sy[DI];
    __shared__ float part8[8][CC];
    __shared__ float rs[6], rq[6];
    int b = blockIdx.x / LL, p = blockIdx.x % LL;
    int h = p / WW, w = p % WW;
    int l1 = w * HH + h;
    int d = threadIdx.x;
    size_t base = (size_t)b * KK * LL * DI;
    // all four direction-gathers of the skip input u land on the same pixel:
    // sum_k D_k[d]*u_k = (sum_k D_k[d]) * xconv[b,d,p]
    float y = g_y[base + ((size_t)0*LL + p)           *DI + d]
            + g_y[base + ((size_t)2*LL + (LL-1-p))    *DI + d]
            + g_y[base + ((size_t)1*LL + l1)          *DI + d]
            + g_y[base + ((size_t)3*LL + (LL-1-l1))   *DI + d]
            + g_sumD[d] * g_xconv[((size_t)b*DI + d)*LL + p];
    float s1 = y, s2 = y*y;
    #pragma unroll
    for (int o = 16; o; o >>= 1) {
        s1 += __shfl_xor_sync(0xffffffffu, s1, o);
        s2 += __shfl_xor_sync(0xffffffffu, s2, o);
    }
    int lane = d & 31, wd = d >> 5;
    if (lane == 0) { rs[wd] = s1; rq[wd] = s2; }
    __syncthreads();
    float tot = 0.f, totq = 0.f;
    #pragma unroll
    for (int i = 0; i < 6; i++) { tot += rs[i]; totq += rq[i]; }
    float mu  = tot  * (1.f/DI);
    float var = totq * (1.f/DI) - mu*mu;
    float inv = rsqrtf(var + 1e-5f);
    float yn = (y - mu) * inv * lnw[d] + lnb[d];
    yn *= g_z[((size_t)b*LL + p)*DI + d];
    sy[d] = yn;
    __syncthreads();

    int q = d / 24, m = d % 24;
    const float4* wt = (const float4*)g_opwT + (size_t)q*24*24 + m;
    float4 acc = make_float4(0.f, 0.f, 0.f, 0.f);
    #pragma unroll 6
    for (int j = 0; j < 24; j++) {
        float sv = sy[q*24 + j];
        float4 wv = wt[(size_t)j*24];
        acc.x = fmaf(wv.x, sv, acc.x);
        acc.y = fmaf(wv.y, sv, acc.y);
        acc.z = fmaf(wv.z, sv, acc.z);
        acc.w = fmaf(wv.w, sv, acc.w);
    }
    *(float4*)&part8[q][4*m] = acc;
    __syncthreads();
    if (d < CC) {
        float s = 0.f;
        #pragma unroll
        for (int i = 0; i < 8; i++) s += part8[i][d];
        size_t o = ((size_t)b*LL + p)*CC + d;
        out[o] = x[o] + s;
    }
}

extern "C" void kernel_launch(void* const* d_in, const int* in_sizes, int n_in,
                              void* d_out, int out_size) {
    const float* x    = (const float*)d_in[0];
    const float* ipw  = (const float*)d_in[1];
    const float* cw   = (const float*)d_in[2];
    const float* cb   = (const float*)d_in[3];
    const float* xpw  = (const float*)d_in[4];
    const float* dtw  = (const float*)d_in[5];
    const float* dtb  = (const float*)d_in[6];
    const float* alog = (const float*)d_in[7];
    const float* dsv  = (const float*)d_in[8];
    const float* lnw  = (const float*)d_in[9];
    const float* lnb  = (const float*)d_in[10];
    const float* opw  = (const float*)d_in[11];
    float* out = (float*)d_out;

    k0_transpose<<<(DI*CC + 255)/256, 256>>>(opw, dsv);

    dim3 g1(BB * (LL/32), 8);
    k1_inproj<<<g1, 256>>>(x, ipw);

    k2_conv<<<BB*DI, 256>>>(cw, cb);

    k3_xproj<<<BB*KK*(LL/32), 256>>>(xpw);

    k4_delta<<<(BB*KK*DI*LL + 255)/256, 256>>>(dtw, dtb);

    dim3 gs1(BB*KK*DI/4, NCH-1);
    k5a_pass1<<<gs1, 128>>>(alog);
    k5b_combine<<<BB*KK*DI/128, 128>>>();
    dim3 gs2(BB*KK*DI/4, NCH);
    k5c_pass2<<<gs2, 128>>>(alog);

    k6_out<<<BB*LL, 192>>>(x, lnw, lnb, out);

    (void)in_sizes; (void)n_in; (void)out_size;
}